// round 12
// baseline (speedup 1.0000x reference)
#include <cuda_runtime.h>
#include <cuda_bf16.h>

// Problem dims (fixed by the dataset)
#define B  512
#define T  1024
#define IN 128
#define H  256

// ---------------- scratch (device globals: no allocation allowed) -------------
__device__ float    g_cur1[(size_t)B * T * H];   // [B][T][H]  512 MB
__device__ float    g_w2t[H * H];                // [j][h]  (W2 transposed)
__device__ unsigned g_spk[(size_t)B * T * 8];    // spk2 ballots, 16 MB

// packed fp32x2 helpers (sm_103a — only reachable via PTX)
#define FMA2(acc, a, b) \
    asm("fma.rn.f32x2 %0, %1, %2, %0;" : "+l"(acc) : "l"(a), "l"(b))
#define ADD2(d, a, b) \
    asm("add.rn.f32x2 %0, %1, %2;" : "=l"(d) : "l"(a), "l"(b))
#define PACK2(d, f) \
    asm("mov.b64 %0, {%1, %1};" : "=l"(d) : "r"(__float_as_uint(f)))

// probe: trailing no-op launch to shift ncu's skip-count onto gemm_cur1
__global__ void probe_kernel() {}

// ---------------- phase 1: cur1 = x @ W1^T + b1 -------------------------------
// 128x128 tile, K-stages of 32, 8x8 micro-tile (rows/cols split 0/64), FFMA2.
// Inner loop: 4 LDS.128 per k-step, ALL conflict-free:
//   a: xs_t[k][ty*4], xs_t[k][64+ty*4]  (lanes 0-15 broadcast)
//   b: ws [k][tx*4], ws [k][64+tx*4]   (lanes contiguous 256B)
// (previous layout had b at 32B lane stride -> 4-way bank conflict -> L1 96.5%)
#define BM  128
#define BN  128
#define BKK 32
#define STR 132          // smem row stride (floats), %4==0 for float4 fills

__global__ void __launch_bounds__(256) gemm_cur1(const float* __restrict__ x,
                                                 const float* __restrict__ W1,
                                                 const float* __restrict__ b1,
                                                 const float* __restrict__ W2) {
    __shared__ float xs_t[BKK][STR];   // [k][bt]
    __shared__ float ws[BKK][STR];     // [k][h]

    const int tid = threadIdx.x;

    if (blockIdx.x == 0) {                      // W2 transpose side-work (2 blocks)
        int base = blockIdx.y * 256 + tid;
        #pragma unroll 4
        for (int i = 0; i < 128; i++) {
            int idx = base + i * 512;
            g_w2t[(idx & 255) * H + (idx >> 8)] = W2[idx];
        }
    }

    const int bm = blockIdx.x * BM;
    const int bn = blockIdx.y * BN;
    const int tx = tid & 15;        // col quads tx*4 and 64+tx*4
    const int ty = tid >> 4;        // row quads ty*4 and 64+ty*4

    unsigned long long acc[8][4];
    #pragma unroll
    for (int r = 0; r < 8; r++)
        #pragma unroll
        for (int p = 0; p < 4; p++) acc[r][p] = 0ull;

    for (int k0 = 0; k0 < IN; k0 += BKK) {
        // fill xs_t[k][bt] = x[bm+bt][k0+k] (transpose; LDG coalesced over k)
        #pragma unroll
        for (int l = 0; l < 4; l++) {
            int k  = tid & 31;
            int qq = (tid >> 5) + l * 8;        // 0..31, bt quad
            const float* xp = &x[(size_t)(bm + qq * 4) * IN + k0 + k];
            float4 v;
            v.x = xp[0 * IN];
            v.y = xp[1 * IN];
            v.z = xp[2 * IN];
            v.w = xp[3 * IN];
            *(float4*)&xs_t[k][qq * 4] = v;
        }
        // fill ws[k][h] = W1[bn+h][k0+k]
        #pragma unroll
        for (int l = 0; l < 4; l++) {
            int k  = tid & 31;
            int hq = (tid >> 5) + l * 8;        // 0..31, h quad
            const float* w1p = &W1[(size_t)(bn + hq * 4) * IN + k0 + k];
            float4 v;
            v.x = w1p[0 * IN];
            v.y = w1p[1 * IN];
            v.z = w1p[2 * IN];
            v.w = w1p[3 * IN];
            *(float4*)&ws[k][hq * 4] = v;
        }
        __syncthreads();

        #pragma unroll 8
        for (int k = 0; k < BKK; k++) {
            float4 a0v = *(float4*)&xs_t[k][ty * 4];
            float4 a1v = *(float4*)&xs_t[k][64 + ty * 4];
            ulonglong2 bv0 = *(ulonglong2*)&ws[k][tx * 4];        // cols tx*4..+3
            ulonglong2 bv1 = *(ulonglong2*)&ws[k][64 + tx * 4];   // cols 64+tx*4..
            unsigned long long A[8];
            PACK2(A[0], a0v.x); PACK2(A[1], a0v.y);
            PACK2(A[2], a0v.z); PACK2(A[3], a0v.w);
            PACK2(A[4], a1v.x); PACK2(A[5], a1v.y);
            PACK2(A[6], a1v.z); PACK2(A[7], a1v.w);
            #pragma unroll
            for (int r = 0; r < 8; r++) {
                FMA2(acc[r][0], A[r], bv0.x);
                FMA2(acc[r][1], A[r], bv0.y);
                FMA2(acc[r][2], A[r], bv1.x);
                FMA2(acc[r][3], A[r], bv1.y);
            }
        }
        __syncthreads();
    }

    // bias + store: rows {bm+ty*4+i, bm+64+ty*4+i}, cols {bn+tx*4.., bn+64+tx*4..}
    ulonglong2 bias0 = *(const ulonglong2*)&b1[bn + tx * 4];
    ulonglong2 bias1 = *(const ulonglong2*)&b1[bn + 64 + tx * 4];
    #pragma unroll
    for (int r = 0; r < 8; r++) {
        int row = bm + ((r < 4) ? (ty * 4 + r) : (64 + ty * 4 + r - 4));
        ulonglong2 o0, o1;
        ADD2(o0.x, acc[r][0], bias0.x);
        ADD2(o0.y, acc[r][1], bias0.y);
        ADD2(o1.x, acc[r][2], bias1.x);
        ADD2(o1.y, acc[r][3], bias1.y);
        float* dst = &g_cur1[(size_t)row * H + bn];
        *(ulonglong2*)(dst + tx * 4)      = o0;
        *(ulonglong2*)(dst + 64 + tx * 4) = o1;
    }
}

// ---------------- phase 2: sequential scan, one CTA per batch element ---------
// (frozen at R8/R9 state)
__global__ void __launch_bounds__(256) scan_kernel(const float* __restrict__ b2,
                                                   const float* __restrict__ wout,
                                                   const float* __restrict__ boutp,
                                                   const float* __restrict__ pb1,
                                                   const float* __restrict__ pb2,
                                                   const float* __restrict__ pbo,
                                                   float* __restrict__ out) {
    const int b    = blockIdx.x;
    const int tid  = threadIdx.x;
    const int lane = tid & 31;
    const int wid  = tid >> 5;

    const float bt1 = fminf(fmaxf(pb1[0], 0.f), 1.f);
    const float bt2 = fminf(fmaxf(pb2[0], 0.f), 1.f);
    const float bto = fminf(fmaxf(pbo[0], 0.f), 1.f);
    const float boutv = boutp[0];
    const float b2v   = b2[tid];

    __shared__ float part[2][8][H];      // double-buffered partials (16KB)
    __shared__ float wout_sm[H];         // 1KB

    wout_sm[tid] = wout[tid];

    float mem1 = 0.f, mem2 = 0.f;
    float s1p = 0.f, s2p = 0.f;

    const float* c1p  = g_cur1 + (size_t)b * T * H + tid;
    unsigned*    spkp = g_spk + (size_t)b * T * 8;
    float*       outp = out + (size_t)b * T;
    const float* rbase = g_w2t + (size_t)(32 * wid) * H + lane * 4;

    float c0 = c1p[0 * H];
    float c1r = c1p[1 * H];
    float c2 = c1p[2 * H];
    float c3 = c1p[3 * H];
    __syncthreads();

    for (int t = 0; t < T; t++) {
        float c1 = c0;
        c0 = c1r; c1r = c2; c2 = c3;
        c3 = (t + 4 < T) ? c1p[(size_t)(t + 4) * H] : 0.f;

        mem1 = bt1 * mem1 + c1 - s1p;
        bool s1 = mem1 > 1.0f;
        unsigned m = __ballot_sync(0xffffffffu, s1);
        s1p = s1 ? 1.f : 0.f;

        ulonglong2 A0, A1, B0, B1;
        A0.x = A0.y = A1.x = A1.y = 0ull;
        B0.x = B0.y = B1.x = B1.y = 0ull;
        while (m) {
            int j0 = __ffs(m) - 1; m &= m - 1;
            const float* p0 = rbase + (size_t)j0 * H;
            if (m) {
                int j1 = __ffs(m) - 1; m &= m - 1;
                const float* p1 = rbase + (size_t)j1 * H;
                ulonglong2 w00 = *(const ulonglong2*)p0;
                ulonglong2 w01 = *(const ulonglong2*)(p0 + 128);
                ulonglong2 w10 = *(const ulonglong2*)p1;
                ulonglong2 w11 = *(const ulonglong2*)(p1 + 128);
                ADD2(A0.x, A0.x, w00.x); ADD2(A0.y, A0.y, w00.y);
                ADD2(A1.x, A1.x, w01.x); ADD2(A1.y, A1.y, w01.y);
                ADD2(B0.x, B0.x, w10.x); ADD2(B0.y, B0.y, w10.y);
                ADD2(B1.x, B1.x, w11.x); ADD2(B1.y, B1.y, w11.y);
            } else {
                ulonglong2 w00 = *(const ulonglong2*)p0;
                ulonglong2 w01 = *(const ulonglong2*)(p0 + 128);
                ADD2(A0.x, A0.x, w00.x); ADD2(A0.y, A0.y, w00.y);
                ADD2(A1.x, A1.x, w01.x); ADD2(A1.y, A1.y, w01.y);
            }
        }
        ADD2(A0.x, A0.x, B0.x); ADD2(A0.y, A0.y, B0.y);
        ADD2(A1.x, A1.x, B1.x); ADD2(A1.y, A1.y, B1.y);
        *(ulonglong2*)&part[t & 1][wid][lane * 4]       = A0;
        *(ulonglong2*)&part[t & 1][wid][128 + lane * 4] = A1;

        __syncthreads();

        const float* pp = &part[t & 1][0][tid];
        float r0 = pp[0 * H] + pp[1 * H];
        float r1 = pp[2 * H] + pp[3 * H];
        float r2 = pp[4 * H] + pp[5 * H];
        float r3 = pp[6 * H] + pp[7 * H];
        float cur2 = b2v + ((r0 + r1) + (r2 + r3));

        mem2 = bt2 * mem2 + cur2 - s2p;
        bool s2 = mem2 > 1.0f;
        s2p = s2 ? 1.f : 0.f;

        unsigned bal2 = __ballot_sync(0xffffffffu, s2);
        if (lane == 0) spkp[(size_t)t * 8 + wid] = bal2;
    }

    // ---------------- deferred output: out_t = bout + sum(spk2 .* wout) -------
    __syncthreads();
    float* out_s = &part[0][0][0];
    #pragma unroll
    for (int i = 0; i < 4; i++) {
        int t = tid + i * 256;
        float o = boutv;
        #pragma unroll
        for (int w = 0; w < 8; w++) {
            unsigned m = spkp[(size_t)t * 8 + w];
            const float* wo = wout_sm + w * 32;
            while (m) {
                int j = __ffs(m) - 1; m &= m - 1;
                o += wo[j];
            }
        }
        out_s[t] = o;
    }
    __syncthreads();
    if (tid == 0) {
        float memo = 0.f;
        for (int t = 0; t < T; t++) {
            memo = bto * memo + out_s[t];
            out_s[t] = memo;
        }
    }
    __syncthreads();
    #pragma unroll
    for (int i = 0; i < 4; i++) {
        int t = tid + i * 256;
        outp[t] = out_s[t];
    }
}

// ---------------- launcher ----------------------------------------------------
extern "C" void kernel_launch(void* const* d_in, const int* in_sizes, int n_in,
                              void* d_out, int out_size) {
    const float* x     = (const float*)d_in[0];   // [B,T,IN]
    const float* W1    = (const float*)d_in[1];   // [H,IN]
    const float* b1    = (const float*)d_in[2];   // [H]
    const float* W2    = (const float*)d_in[3];   // [H,H]
    const float* b2    = (const float*)d_in[4];   // [H]
    const float* Wout  = (const float*)d_in[5];   // [1,H]
    const float* bout  = (const float*)d_in[6];   // [1]
    const float* beta1 = (const float*)d_in[7];
    const float* beta2 = (const float*)d_in[8];
    const float* betao = (const float*)d_in[9];
    float* out = (float*)d_out;                   // [B,T,1]

    dim3 ggrid(B * T / BM, H / BN);
    gemm_cur1<<<ggrid, 256>>>(x, W1, b1, W2);

    scan_kernel<<<B, 256>>>(b2, Wout, bout, beta1, beta2, betao, out);

    probe_kernel<<<1, 32>>>();   // parity-shift so ncu skip-5 lands on gemm_cur1
}

// round 13
// speedup vs baseline: 1.5382x; 1.5382x over previous
#include <cuda_runtime.h>
#include <cuda_bf16.h>

// Problem dims (fixed by the dataset)
#define B  512
#define T  1024
#define IN 128
#define H  256

// ---------------- scratch (device globals: no allocation allowed) -------------
__device__ float    g_cur1[(size_t)B * T * H];   // [B][T][H]  512 MB
__device__ float    g_cur2[(size_t)B * T * H];   // [B][T][H]  512 MB
__device__ float    g_w2t[H * H];                // [j][h]  (W2 transposed)
__device__ unsigned g_spk1[(size_t)B * T * 8];   // spk1 ballots, 16 MB
__device__ unsigned g_spk2[(size_t)B * T * 8];   // spk2 ballots, 16 MB

// packed fp32x2 helpers (sm_103a — only reachable via PTX)
#define FMA2(acc, a, b) \
    asm("fma.rn.f32x2 %0, %1, %2, %0;" : "+l"(acc) : "l"(a), "l"(b))
#define ADD2(d, a, b) \
    asm("add.rn.f32x2 %0, %1, %2;" : "=l"(d) : "l"(a), "l"(b))
#define PACK2(d, f) \
    asm("mov.b64 %0, {%1, %1};" : "=l"(d) : "r"(__float_as_uint(f)))

// probe: no-op launch placed so ncu skip-5 lands on cur2_kernel
__global__ void probe_kernel() {}

// ---------------- phase 1: cur1 = x @ W1^T + b1 (proven R12 kernel) -----------
#define BM  128
#define BN  128
#define BKK 32
#define STR 132

__global__ void __launch_bounds__(256) gemm_cur1(const float* __restrict__ x,
                                                 const float* __restrict__ W1,
                                                 const float* __restrict__ b1,
                                                 const float* __restrict__ W2) {
    __shared__ float xs_t[BKK][STR];   // [k][bt]
    __shared__ float ws[BKK][STR];     // [k][h]

    const int tid = threadIdx.x;

    if (blockIdx.x == 0) {                      // W2 transpose side-work (2 blocks)
        int base = blockIdx.y * 256 + tid;
        #pragma unroll 4
        for (int i = 0; i < 128; i++) {
            int idx = base + i * 512;
            g_w2t[(idx & 255) * H + (idx >> 8)] = W2[idx];
        }
    }

    const int bm = blockIdx.x * BM;
    const int bn = blockIdx.y * BN;
    const int tx = tid & 15;
    const int ty = tid >> 4;

    unsigned long long acc[8][4];
    #pragma unroll
    for (int r = 0; r < 8; r++)
        #pragma unroll
        for (int p = 0; p < 4; p++) acc[r][p] = 0ull;

    for (int k0 = 0; k0 < IN; k0 += BKK) {
        #pragma unroll
        for (int l = 0; l < 4; l++) {
            int k  = tid & 31;
            int qq = (tid >> 5) + l * 8;
            const float* xp = &x[(size_t)(bm + qq * 4) * IN + k0 + k];
            float4 v;
            v.x = xp[0 * IN];
            v.y = xp[1 * IN];
            v.z = xp[2 * IN];
            v.w = xp[3 * IN];
            *(float4*)&xs_t[k][qq * 4] = v;
        }
        #pragma unroll
        for (int l = 0; l < 4; l++) {
            int k  = tid & 31;
            int hq = (tid >> 5) + l * 8;
            const float* w1p = &W1[(size_t)(bn + hq * 4) * IN + k0 + k];
            float4 v;
            v.x = w1p[0 * IN];
            v.y = w1p[1 * IN];
            v.z = w1p[2 * IN];
            v.w = w1p[3 * IN];
            *(float4*)&ws[k][hq * 4] = v;
        }
        __syncthreads();

        #pragma unroll 8
        for (int k = 0; k < BKK; k++) {
            float4 a0v = *(float4*)&xs_t[k][ty * 4];
            float4 a1v = *(float4*)&xs_t[k][64 + ty * 4];
            ulonglong2 bv0 = *(ulonglong2*)&ws[k][tx * 4];
            ulonglong2 bv1 = *(ulonglong2*)&ws[k][64 + tx * 4];
            unsigned long long A[8];
            PACK2(A[0], a0v.x); PACK2(A[1], a0v.y);
            PACK2(A[2], a0v.z); PACK2(A[3], a0v.w);
            PACK2(A[4], a1v.x); PACK2(A[5], a1v.y);
            PACK2(A[6], a1v.z); PACK2(A[7], a1v.w);
            #pragma unroll
            for (int r = 0; r < 8; r++) {
                FMA2(acc[r][0], A[r], bv0.x);
                FMA2(acc[r][1], A[r], bv0.y);
                FMA2(acc[r][2], A[r], bv1.x);
                FMA2(acc[r][3], A[r], bv1.y);
            }
        }
        __syncthreads();
    }

    ulonglong2 bias0 = *(const ulonglong2*)&b1[bn + tx * 4];
    ulonglong2 bias1 = *(const ulonglong2*)&b1[bn + 64 + tx * 4];
    #pragma unroll
    for (int r = 0; r < 8; r++) {
        int row = bm + ((r < 4) ? (ty * 4 + r) : (64 + ty * 4 + r - 4));
        ulonglong2 o0, o1;
        ADD2(o0.x, acc[r][0], bias0.x);
        ADD2(o0.y, acc[r][1], bias0.y);
        ADD2(o1.x, acc[r][2], bias1.x);
        ADD2(o1.y, acc[r][3], bias1.y);
        float* dst = &g_cur1[(size_t)row * H + bn];
        *(ulonglong2*)(dst + tx * 4)      = o0;
        *(ulonglong2*)(dst + 64 + tx * 4) = o1;
    }
}

// ---------------- phase A: layer-1 recurrence -> spk1 ballots -----------------
// Per-(b,h) independent. One CTA per batch, thread = neuron, NO barriers.
// cur1 streamed 8-deep (group double-buffer) -> DRAM-bound (~80us).
__global__ void __launch_bounds__(256) spike1_kernel(const float* __restrict__ pb1) {
    const int b    = blockIdx.x;
    const int tid  = threadIdx.x;
    const int lane = tid & 31;
    const int wid  = tid >> 5;

    const float bt1 = fminf(fmaxf(pb1[0], 0.f), 1.f);
    const float* c1p = g_cur1 + (size_t)b * T * H + tid;
    unsigned*    sp  = g_spk1 + (size_t)b * T * 8;

    float mem1 = 0.f, s1p = 0.f;

    float cur[8], nxt[8];
    #pragma unroll
    for (int i = 0; i < 8; i++) cur[i] = c1p[(size_t)i * H];

    for (int t0 = 0; t0 < T; t0 += 8) {
        #pragma unroll
        for (int i = 0; i < 8; i++)
            nxt[i] = (t0 + 8 + i < T) ? c1p[(size_t)(t0 + 8 + i) * H] : 0.f;

        #pragma unroll
        for (int i = 0; i < 8; i++) {
            mem1 = bt1 * mem1 + cur[i] - s1p;
            bool s1 = mem1 > 1.0f;
            unsigned bal = __ballot_sync(0xffffffffu, s1);
            if (lane == 0) sp[(size_t)(t0 + i) * 8 + wid] = bal;
            s1p = s1 ? 1.f : 0.f;
        }
        #pragma unroll
        for (int i = 0; i < 8; i++) cur[i] = nxt[i];
    }
}

// ---------------- phase B: cur2[b][t][:] = b2 + sum_{spk1 bits} W2T rows ------
// FULLY parallel over (b, t): one warp per timestep, 8 warps/CTA, no barriers,
// no recurrence -> L1 gather pipe can saturate. Lane l owns cols [4l,4l+4) and
// [128+4l,..): warp-contiguous 512B loads (min wavefronts). 2 rows in flight.
__global__ void __launch_bounds__(256) cur2_kernel(const float* __restrict__ b2) {
    const int b    = blockIdx.x;
    const int wid  = threadIdx.x >> 5;
    const int lane = threadIdx.x & 31;
    const int t    = blockIdx.y * 8 + wid;

    const unsigned* sp = g_spk1 + ((size_t)b * T + t) * 8;

    ulonglong2 A0 = *(const ulonglong2*)&b2[lane * 4];        // init with bias
    ulonglong2 A1 = *(const ulonglong2*)&b2[128 + lane * 4];
    ulonglong2 B0, B1;
    B0.x = B0.y = B1.x = B1.y = 0ull;

    #pragma unroll
    for (int w = 0; w < 8; w++) {
        unsigned m = sp[w];
        const float* rbase = g_w2t + (size_t)(32 * w) * H + lane * 4;
        while (m) {
            int j0 = __ffs(m) - 1; m &= m - 1;
            const float* p0 = rbase + (size_t)j0 * H;
            if (m) {
                int j1 = __ffs(m) - 1; m &= m - 1;
                const float* p1 = rbase + (size_t)j1 * H;
                ulonglong2 w00 = *(const ulonglong2*)p0;
                ulonglong2 w01 = *(const ulonglong2*)(p0 + 128);
                ulonglong2 w10 = *(const ulonglong2*)p1;
                ulonglong2 w11 = *(const ulonglong2*)(p1 + 128);
                ADD2(A0.x, A0.x, w00.x); ADD2(A0.y, A0.y, w00.y);
                ADD2(A1.x, A1.x, w01.x); ADD2(A1.y, A1.y, w01.y);
                ADD2(B0.x, B0.x, w10.x); ADD2(B0.y, B0.y, w10.y);
                ADD2(B1.x, B1.x, w11.x); ADD2(B1.y, B1.y, w11.y);
            } else {
                ulonglong2 w00 = *(const ulonglong2*)p0;
                ulonglong2 w01 = *(const ulonglong2*)(p0 + 128);
                ADD2(A0.x, A0.x, w00.x); ADD2(A0.y, A0.y, w00.y);
                ADD2(A1.x, A1.x, w01.x); ADD2(A1.y, A1.y, w01.y);
            }
        }
    }
    ADD2(A0.x, A0.x, B0.x); ADD2(A0.y, A0.y, B0.y);
    ADD2(A1.x, A1.x, B1.x); ADD2(A1.y, A1.y, B1.y);

    float* dst = g_cur2 + ((size_t)b * T + t) * H;
    *(ulonglong2*)(dst + lane * 4)       = A0;
    *(ulonglong2*)(dst + 128 + lane * 4) = A1;
}

// ---------------- phase C+D: layer-2 recurrence + deferred output -------------
// Per-(b,h) recurrence over cur2 stream (no gather, no per-step barrier), then
// the deferred out_t reduction + exact serial memo recurrence (as before).
__global__ void __launch_bounds__(256) scan2_kernel(const float* __restrict__ wout,
                                                    const float* __restrict__ boutp,
                                                    const float* __restrict__ pb2,
                                                    const float* __restrict__ pbo,
                                                    float* __restrict__ out) {
    const int b    = blockIdx.x;
    const int tid  = threadIdx.x;
    const int lane = tid & 31;
    const int wid  = tid >> 5;

    const float bt2 = fminf(fmaxf(pb2[0], 0.f), 1.f);
    const float bto = fminf(fmaxf(pbo[0], 0.f), 1.f);
    const float boutv = boutp[0];

    __shared__ float wout_sm[H];
    __shared__ float out_s[T];
    wout_sm[tid] = wout[tid];

    const float* c2p  = g_cur2 + (size_t)b * T * H + tid;
    unsigned*    spkp = g_spk2 + (size_t)b * T * 8;
    float*       outp = out + (size_t)b * T;

    float mem2 = 0.f, s2p = 0.f;

    float cur[8], nxt[8];
    #pragma unroll
    for (int i = 0; i < 8; i++) cur[i] = c2p[(size_t)i * H];

    for (int t0 = 0; t0 < T; t0 += 8) {
        #pragma unroll
        for (int i = 0; i < 8; i++)
            nxt[i] = (t0 + 8 + i < T) ? c2p[(size_t)(t0 + 8 + i) * H] : 0.f;

        #pragma unroll
        for (int i = 0; i < 8; i++) {
            mem2 = bt2 * mem2 + cur[i] - s2p;
            bool s2 = mem2 > 1.0f;
            unsigned bal = __ballot_sync(0xffffffffu, s2);
            if (lane == 0) spkp[(size_t)(t0 + i) * 8 + wid] = bal;
            s2p = s2 ? 1.f : 0.f;
        }
        #pragma unroll
        for (int i = 0; i < 8; i++) cur[i] = nxt[i];
    }

    // deferred output: out_t = bout + sum(spk2 .* wout); then memo recurrence
    __syncthreads();   // spk2 ballots + wout_sm visible block-wide
    #pragma unroll
    for (int i = 0; i < 4; i++) {
        int t = tid + i * 256;
        float o = boutv;
        #pragma unroll
        for (int w = 0; w < 8; w++) {
            unsigned m = spkp[(size_t)t * 8 + w];
            const float* wo = wout_sm + w * 32;
            while (m) {
                int j = __ffs(m) - 1; m &= m - 1;
                o += wo[j];
            }
        }
        out_s[t] = o;
    }
    __syncthreads();
    if (tid == 0) {                               // exact serial memo recurrence
        float memo = 0.f;
        for (int t = 0; t < T; t++) {
            memo = bto * memo + out_s[t];
            out_s[t] = memo;
        }
    }
    __syncthreads();
    #pragma unroll
    for (int i = 0; i < 4; i++) {
        int t = tid + i * 256;
        outp[t] = out_s[t];
    }
}

// ---------------- launcher ----------------------------------------------------
extern "C" void kernel_launch(void* const* d_in, const int* in_sizes, int n_in,
                              void* d_out, int out_size) {
    const float* x     = (const float*)d_in[0];   // [B,T,IN]
    const float* W1    = (const float*)d_in[1];   // [H,IN]
    const float* b1    = (const float*)d_in[2];   // [H]
    const float* W2    = (const float*)d_in[3];   // [H,H]
    const float* b2    = (const float*)d_in[4];   // [H]
    const float* Wout  = (const float*)d_in[5];   // [1,H]
    const float* bout  = (const float*)d_in[6];   // [1]
    const float* beta1 = (const float*)d_in[7];
    const float* beta2 = (const float*)d_in[8];
    const float* betao = (const float*)d_in[9];
    float* out = (float*)d_out;                   // [B,T,1]

    dim3 ggrid(B * T / BM, H / BN);
    gemm_cur1<<<ggrid, 256>>>(x, W1, b1, W2);

    spike1_kernel<<<B, 256>>>(beta1);

    probe_kernel<<<1, 32>>>();   // placed so ncu skip-5 profiles cur2_kernel

    dim3 cgrid(B, T / 8);
    cur2_kernel<<<cgrid, 256>>>(b2);

    scan2_kernel<<<B, 256>>>(Wout, bout, beta2, betao, out);
}